// round 1
// baseline (speedup 1.0000x reference)
#include <cuda_runtime.h>
#include <cuda_bf16.h>

#define BSZ 2
#define LSEQ 2048
#define DMODEL 1024
#define NH 16
#define DH 64

// Scratch (allocation-free rule: __device__ globals)
__device__ float g_Q[(size_t)BSZ * NH * LSEQ * DH];   // [B,H,L,Dh]
__device__ float g_K[(size_t)BSZ * NH * LSEQ * DH];   // [B,H,L,Dh]
__device__ float g_V[(size_t)BSZ * NH * LSEQ * DH];   // [B,H,L,Dh]
__device__ float g_O[(size_t)BSZ * LSEQ * NH * DH];   // [B,L,H,Dh]

// ---------------------------------------------------------------------------
// Fused QKV projection: X[4096,1024] x W*[1024,1024] -> Q/K/V [B,H,L,Dh]
// BM=BN=64, BK=16, 256 threads, 4x4 per-thread tile, 3 accumulators.
// ---------------------------------------------------------------------------
__global__ __launch_bounds__(256) void qkv_kernel(
    const float* __restrict__ x,
    const float* __restrict__ Wq,
    const float* __restrict__ Wk,
    const float* __restrict__ Wv)
{
    __shared__ __align__(16) float As[16][68];   // [kk][row] (transposed)
    __shared__ __align__(16) float Bqs[16][68];  // [kk][col]
    __shared__ __align__(16) float Bks[16][68];
    __shared__ __align__(16) float Bvs[16][68];

    const int tx = threadIdx.x, ty = threadIdx.y;
    const int tid = ty * 16 + tx;
    const int row0 = blockIdx.y * 64;
    const int col0 = blockIdx.x * 64;

    float accQ[4][4] = {}, accK[4][4] = {}, accV[4][4] = {};

    const int lr  = tid >> 2;          // 0..63 (A row)
    const int lk  = (tid & 3) * 4;     // 0..12 (A k offset)
    const int lkr = tid >> 4;          // 0..15 (B k row)
    const int lc  = (tid & 15) * 4;    // 0..60 (B col offset)

    for (int k0 = 0; k0 < DMODEL; k0 += 16) {
        float4 av = *(const float4*)(x + (size_t)(row0 + lr) * DMODEL + k0 + lk);
        As[lk + 0][lr] = av.x;
        As[lk + 1][lr] = av.y;
        As[lk + 2][lr] = av.z;
        As[lk + 3][lr] = av.w;

        *(float4*)&Bqs[lkr][lc] = *(const float4*)(Wq + (size_t)(k0 + lkr) * DMODEL + col0 + lc);
        *(float4*)&Bks[lkr][lc] = *(const float4*)(Wk + (size_t)(k0 + lkr) * DMODEL + col0 + lc);
        *(float4*)&Bvs[lkr][lc] = *(const float4*)(Wv + (size_t)(k0 + lkr) * DMODEL + col0 + lc);
        __syncthreads();

        #pragma unroll
        for (int kk = 0; kk < 16; kk++) {
            float4 a4 = *(const float4*)&As[kk][ty * 4];
            float4 q4 = *(const float4*)&Bqs[kk][tx * 4];
            float4 k4 = *(const float4*)&Bks[kk][tx * 4];
            float4 v4 = *(const float4*)&Bvs[kk][tx * 4];
            float a[4] = {a4.x, a4.y, a4.z, a4.w};
            float bq[4] = {q4.x, q4.y, q4.z, q4.w};
            float bk[4] = {k4.x, k4.y, k4.z, k4.w};
            float bv[4] = {v4.x, v4.y, v4.z, v4.w};
            #pragma unroll
            for (int i = 0; i < 4; i++) {
                #pragma unroll
                for (int j = 0; j < 4; j++) {
                    accQ[i][j] += a[i] * bq[j];
                    accK[i][j] += a[i] * bk[j];
                    accV[i][j] += a[i] * bv[j];
                }
            }
        }
        __syncthreads();
    }

    // Write out. One N-tile spans exactly one head (col0 multiple of 64).
    const int h = col0 >> 6;
    #pragma unroll
    for (int i = 0; i < 4; i++) {
        const int m = row0 + ty * 4 + i;       // global row = b*L + l
        const int b = m >> 11;                  // L = 2048
        const int l = m & (LSEQ - 1);
        const size_t base = (((size_t)b * NH + h) * LSEQ + l) * DH + tx * 4;
        *(float4*)(g_Q + base) = make_float4(accQ[i][0], accQ[i][1], accQ[i][2], accQ[i][3]);
        *(float4*)(g_K + base) = make_float4(accK[i][0], accK[i][1], accK[i][2], accK[i][3]);
        *(float4*)(g_V + base) = make_float4(accV[i][0], accV[i][1], accV[i][2], accV[i][3]);
    }
}

// ---------------------------------------------------------------------------
// Flash attention forward (causal), 64 q-rows x Dh=64 per block, K-tiles of 64.
// 256 threads (16x16), online softmax. Dynamic smem: 4 x 64x65 tiles + rows.
// ---------------------------------------------------------------------------
__global__ __launch_bounds__(256) void attn_kernel()
{
    extern __shared__ float sm[];
    float* Qs = sm;                 // [64][65]
    float* Ks = Qs + 64 * 65;       // [64][65]  (key-major: [k][d])
    float* Vs = Ks + 64 * 65;       // [64][65]  ([k][d])
    float* Ps = Vs + 64 * 65;       // [64][65]
    float* row_m = Ps + 64 * 65;    // [64]
    float* row_l = row_m + 64;      // [64]

    const int tx = threadIdx.x, ty = threadIdx.y;
    const int tid = ty * 16 + tx;
    const int qt = blockIdx.x;      // q tile 0..31
    const int h  = blockIdx.y;
    const int b  = blockIdx.z;
    const int q0 = qt * 64;

    const float* Qg = g_Q + (((size_t)b * NH + h) * LSEQ) * DH;
    const float* Kg = g_K + (((size_t)b * NH + h) * LSEQ) * DH;
    const float* Vg = g_V + (((size_t)b * NH + h) * LSEQ) * DH;

    // Load Q tile
    for (int i = tid; i < 64 * 64; i += 256) {
        int r = i >> 6, c = i & 63;
        Qs[r * 65 + c] = Qg[(size_t)(q0 + r) * DH + c];
    }
    if (tid < 64) { row_m[tid] = -1e30f; row_l[tid] = 0.0f; }

    float acc[4][4] = {};

    for (int j = 0; j <= qt; j++) {
        __syncthreads();  // protect Ks/Vs/Ps from previous iteration
        const int k0 = j * 64;
        for (int i = tid; i < 64 * 64; i += 256) {
            int r = i >> 6, c = i & 63;
            Ks[r * 65 + c] = Kg[(size_t)(k0 + r) * DH + c];
            Vs[r * 65 + c] = Vg[(size_t)(k0 + r) * DH + c];
        }
        __syncthreads();

        // S = Q * K^T   (4x4 per thread)
        float s[4][4] = {};
        #pragma unroll 16
        for (int kk = 0; kk < 64; kk++) {
            float a[4], bb[4];
            #pragma unroll
            for (int i2 = 0; i2 < 4; i2++) a[i2] = Qs[(ty * 4 + i2) * 65 + kk];
            #pragma unroll
            for (int j2 = 0; j2 < 4; j2++) bb[j2] = Ks[(tx * 4 + j2) * 65 + kk];
            #pragma unroll
            for (int i2 = 0; i2 < 4; i2++)
                #pragma unroll
                for (int j2 = 0; j2 < 4; j2++)
                    s[i2][j2] += a[i2] * bb[j2];
        }

        // scale + causal mask (only the diagonal tile has masked entries)
        const bool diag = (j == qt);
        #pragma unroll
        for (int i2 = 0; i2 < 4; i2++)
            #pragma unroll
            for (int j2 = 0; j2 < 4; j2++) {
                float v = s[i2][j2] * 0.125f;  // 1/sqrt(64)
                if (diag && (tx * 4 + j2 > ty * 4 + i2)) v = -1e30f;
                s[i2][j2] = v;
            }

        // Online softmax: rows ty*4+i2, reduced across the 16 tx lanes (in-warp)
        #pragma unroll
        for (int i2 = 0; i2 < 4; i2++) {
            const int r = ty * 4 + i2;
            float m = fmaxf(fmaxf(s[i2][0], s[i2][1]), fmaxf(s[i2][2], s[i2][3]));
            #pragma unroll
            for (int off = 8; off >= 1; off >>= 1)
                m = fmaxf(m, __shfl_xor_sync(0xffffffffu, m, off));
            const float mold = row_m[r];
            const float mnew = fmaxf(mold, m);
            float p[4], lsum = 0.0f;
            #pragma unroll
            for (int j2 = 0; j2 < 4; j2++) { p[j2] = __expf(s[i2][j2] - mnew); lsum += p[j2]; }
            #pragma unroll
            for (int off = 8; off >= 1; off >>= 1)
                lsum += __shfl_xor_sync(0xffffffffu, lsum, off);
            const float scale = __expf(mold - mnew);
            if (tx == 0) { row_m[r] = mnew; row_l[r] = row_l[r] * scale + lsum; }
            #pragma unroll
            for (int j2 = 0; j2 < 4; j2++) acc[i2][j2] *= scale;
            #pragma unroll
            for (int j2 = 0; j2 < 4; j2++) Ps[r * 65 + tx * 4 + j2] = p[j2];
        }
        __syncthreads();

        // O += P * V
        #pragma unroll 16
        for (int kk = 0; kk < 64; kk++) {
            float a[4], bb[4];
            #pragma unroll
            for (int i2 = 0; i2 < 4; i2++) a[i2] = Ps[(ty * 4 + i2) * 65 + kk];
            #pragma unroll
            for (int j2 = 0; j2 < 4; j2++) bb[j2] = Vs[kk * 65 + tx * 4 + j2];
            #pragma unroll
            for (int i2 = 0; i2 < 4; i2++)
                #pragma unroll
                for (int j2 = 0; j2 < 4; j2++)
                    acc[i2][j2] += a[i2] * bb[j2];
        }
    }
    __syncthreads();

    // Epilogue: O[b, l, h, e] = acc / row_l
    float* Og = g_O + ((size_t)b * LSEQ) * (NH * DH) + h * DH;
    #pragma unroll
    for (int i2 = 0; i2 < 4; i2++) {
        const int r = ty * 4 + i2;
        const float inv = 1.0f / row_l[r];
        #pragma unroll
        for (int j2 = 0; j2 < 4; j2++)
            Og[(size_t)(q0 + r) * (NH * DH) + tx * 4 + j2] = acc[i2][j2] * inv;
    }
}

// ---------------------------------------------------------------------------
// Output projection: g_O[4096,1024] x Wout[1024,1024] -> out[4096,1024]
// ---------------------------------------------------------------------------
__global__ __launch_bounds__(256) void oproj_kernel(
    const float* __restrict__ Wout,
    float* __restrict__ out)
{
    __shared__ __align__(16) float As[16][68];  // [kk][row]
    __shared__ __align__(16) float Bs[16][68];  // [kk][col]

    const int tx = threadIdx.x, ty = threadIdx.y;
    const int tid = ty * 16 + tx;
    const int row0 = blockIdx.y * 64;
    const int col0 = blockIdx.x * 64;

    float acc[4][4] = {};

    const int lr  = tid >> 2;
    const int lk  = (tid & 3) * 4;
    const int lkr = tid >> 4;
    const int lc  = (tid & 15) * 4;

    const float* A = g_O;  // [4096,1024] row-major view of [B,L,H,Dh]

    for (int k0 = 0; k0 < DMODEL; k0 += 16) {
        float4 av = *(const float4*)(A + (size_t)(row0 + lr) * DMODEL + k0 + lk);
        As[lk + 0][lr] = av.x;
        As[lk + 1][lr] = av.y;
        As[lk + 2][lr] = av.z;
        As[lk + 3][lr] = av.w;
        *(float4*)&Bs[lkr][lc] = *(const float4*)(Wout + (size_t)(k0 + lkr) * DMODEL + col0 + lc);
        __syncthreads();

        #pragma unroll
        for (int kk = 0; kk < 16; kk++) {
            float4 a4 = *(const float4*)&As[kk][ty * 4];
            float4 b4 = *(const float4*)&Bs[kk][tx * 4];
            float a[4] = {a4.x, a4.y, a4.z, a4.w};
            float bb[4] = {b4.x, b4.y, b4.z, b4.w};
            #pragma unroll
            for (int i = 0; i < 4; i++)
                #pragma unroll
                for (int j = 0; j < 4; j++)
                    acc[i][j] += a[i] * bb[j];
        }
        __syncthreads();
    }

    #pragma unroll
    for (int i = 0; i < 4; i++) {
        const int m = row0 + ty * 4 + i;
        *(float4*)(out + (size_t)m * DMODEL + col0 + tx * 4) =
            make_float4(acc[i][0], acc[i][1], acc[i][2], acc[i][3]);
    }
}

// ---------------------------------------------------------------------------
extern "C" void kernel_launch(void* const* d_in, const int* in_sizes, int n_in,
                              void* d_out, int out_size)
{
    const float* x    = (const float*)d_in[0];
    const float* Wq   = (const float*)d_in[1];
    const float* Wk   = (const float*)d_in[2];
    const float* Wv   = (const float*)d_in[3];
    const float* Wout = (const float*)d_in[4];
    float* out = (float*)d_out;

    dim3 blk(16, 16);

    // 1) QKV projection: grid over (N tiles = 16, M tiles = 64)
    qkv_kernel<<<dim3(16, 64), blk>>>(x, Wq, Wk, Wv);

    // 2) Flash attention: (q-tiles=32, H=16, B=2)
    const size_t attn_smem = (size_t)(4 * 64 * 65 + 128) * sizeof(float);
    cudaFuncSetAttribute(attn_kernel, cudaFuncAttributeMaxDynamicSharedMemorySize,
                         (int)attn_smem);
    attn_kernel<<<dim3(32, 16, 2), blk, attn_smem>>>();

    // 3) Output projection
    oproj_kernel<<<dim3(16, 64), blk>>>(Wout, out);
}